// round 1
// baseline (speedup 1.0000x reference)
#include <cuda_runtime.h>
#include <cstdint>

typedef unsigned long long ull;

#define THREADS 256
#define F_TILE  64
#define HALF    257
#define KPAD    258   // 257 padded to even for h-pairing (pad row zeroed)
#define MPAD    66    // row pad: stride 66 words == 2 mod 32 (2-way store conflict max),
                      // keeps 8B alignment for f32x2 pair loads
#define NMELS   64
#define FFT     512

#define FMA2(d, a, b) asm("fma.rn.f32x2 %0, %1, %2, %0;" : "+l"(d) : "l"(a), "l"(b))

__global__ __launch_bounds__(THREADS, 1)
void lmfe_kernel(const float* __restrict__ x, const float* __restrict__ fb,
                 float* __restrict__ out)
{
    extern __shared__ float sm[];
    float* fbT  = sm;                  // [KPAD][MPAD]  fbT[h][m]
    float* magS = sm + KPAD * MPAD;    // [KPAD][MPAD]  magS[h][f_local]

    const int tid   = threadIdx.x;
    const int fbase = blockIdx.x * F_TILE;

    // zero the padded h row (h == 257) so the paired inner loop reads 0 there
    for (int i = tid; i < MPAD; i += THREADS) {
        fbT [(KPAD - 1) * MPAD + i] = 0.f;
        magS[(KPAD - 1) * MPAD + i] = 0.f;
    }

    // filter banks: global [64][257] row-major -> smem transposed fbT[h][m]
    for (int idx = tid; idx < NMELS * HALF; idx += THREADS) {
        int m = idx / HALF;
        int h = idx - m * HALF;
        fbT[h * MPAD + m] = fb[idx];
    }

    // mag = (x + 1)^2, staged transposed: magS[h][f]
    const float* xp = x + (size_t)fbase * FFT;
    for (int idx = tid; idx < F_TILE * HALF; idx += THREADS) {
        int f = idx / HALF;
        int h = idx - f * HALF;
        float v = __ldg(xp + (size_t)f * FFT + h) + 1.0f;
        magS[h * MPAD + f] = v * v;
    }
    __syncthreads();

    const int warp = tid >> 5;
    const int lane = tid & 31;
    const int m0 = warp * 8;   // 8 warps x 8 mels = 64 mels
    const int fl = lane * 2;   // each lane: 2 adjacent local frames

    ull acc0[4] = {0, 0, 0, 0};   // frame fl  : mel pairs (m0+2j, m0+2j+1)
    ull acc1[4] = {0, 0, 0, 0};   // frame fl+1

    const float* mgp = magS + fl;
    const float* fbp = fbT + m0;

    #pragma unroll 4
    for (int h = 0; h < KPAD; ++h) {
        float2 a = *reinterpret_cast<const float2*>(mgp + h * MPAD); // conflict-free LDS.64
        ull p0, p1;
        asm("mov.b64 %0, {%1, %1};" : "=l"(p0) : "f"(a.x));
        asm("mov.b64 %0, {%1, %1};" : "=l"(p1) : "f"(a.y));
        #pragma unroll
        for (int j = 0; j < 4; ++j) {
            // all lanes in warp read the same address -> smem broadcast
            ull b = *reinterpret_cast<const ull*>(fbp + h * MPAD + 2 * j);
            FMA2(acc0[j], p0, b);
            FMA2(acc1[j], p1, b);
        }
    }

    // epilogue: floor(log2(m)) == IEEE exponent of m (exact for positive normals)
    float r0[8], r1[8];
    #pragma unroll
    for (int j = 0; j < 4; ++j) {
        float2 v0, v1;
        asm("mov.b64 {%0, %1}, %2;" : "=f"(v0.x), "=f"(v0.y) : "l"(acc0[j]));
        asm("mov.b64 {%0, %1}, %2;" : "=f"(v1.x), "=f"(v1.y) : "l"(acc1[j]));
        r0[2*j] = v0.x; r0[2*j+1] = v0.y;
        r1[2*j] = v1.x; r1[2*j+1] = v1.y;
    }
    #pragma unroll
    for (int k = 0; k < 8; ++k) {
        r0[k] = (float)(((__float_as_int(r0[k]) >> 23) & 255) - 127);
        r1[k] = (float)(((__float_as_int(r1[k]) >> 23) & 255) - 127);
    }

    size_t g0 = (size_t)(fbase + fl) * NMELS + m0;   // m0 multiple of 8 -> 16B aligned
    float4* o0 = reinterpret_cast<float4*>(out + g0);
    float4* o1 = reinterpret_cast<float4*>(out + g0 + NMELS);
    o0[0] = make_float4(r0[0], r0[1], r0[2], r0[3]);
    o0[1] = make_float4(r0[4], r0[5], r0[6], r0[7]);
    o1[0] = make_float4(r1[0], r1[1], r1[2], r1[3]);
    o1[1] = make_float4(r1[4], r1[5], r1[6], r1[7]);
}

extern "C" void kernel_launch(void* const* d_in, const int* in_sizes, int n_in,
                              void* d_out, int out_size)
{
    const float* x  = (const float*)d_in[0];   // (256,256,512,1) fp32
    const float* fb = (const float*)d_in[1];   // (64,257) fp32
    float* out = (float*)d_out;                // (256,256,64,1) fp32

    const int smem = 2 * KPAD * MPAD * (int)sizeof(float);  // 136224 B
    cudaFuncSetAttribute(lmfe_kernel, cudaFuncAttributeMaxDynamicSharedMemorySize, smem);

    const int nframes = in_sizes[0] / FFT;     // 65536
    const int grid    = nframes / F_TILE;      // 1024
    lmfe_kernel<<<grid, THREADS, smem>>>(x, fb, out);
}

// round 4
// speedup vs baseline: 1.1041x; 1.1041x over previous
#include <cuda_runtime.h>
#include <cstdint>

typedef unsigned long long ull;

#define THREADS 256
#define F_TILE  128
#define HALF    257
#define KPAD    258   // pad h to even (pad row zeroed) for unroll-2
#define MPAD_F  130   // mag row stride (words): bank step 2 -> 2-way conflict max, 8B aligned
#define MPAD_M  66    // fb  row stride (words): bank step 2 -> 2-way conflict max, 8B aligned
#define NMELS   64
#define FFT     512

#define FMA2(d, a, b) asm("fma.rn.f32x2 %0, %1, %2, %0;" : "+l"(d) : "l"(a), "l"(b))

__global__ __launch_bounds__(THREADS, 1)
void lmfe_kernel(const float* __restrict__ x, const float* __restrict__ fb,
                 float* __restrict__ out)
{
    extern __shared__ float sm[];
    float* fbT  = sm;                    // [KPAD][MPAD_M]  fbT[h][m]
    float* magS = sm + KPAD * MPAD_M;    // [KPAD][MPAD_F]  magS[h][f_local]

    const int tid   = threadIdx.x;
    const int fbase = blockIdx.x * F_TILE;

    // zero the padded h row (h == 257)
    for (int i = tid; i < MPAD_M; i += THREADS) fbT [(KPAD-1)*MPAD_M + i] = 0.f;
    for (int i = tid; i < MPAD_F; i += THREADS) magS[(KPAD-1)*MPAD_F + i] = 0.f;

    // filter banks: [64][257] row-major -> fbT[h][m]   (STS stride 66 -> 2-way)
    for (int idx = tid; idx < NMELS * HALF; idx += THREADS) {
        int m = idx / HALF;
        int h = idx - m * HALF;
        fbT[h * MPAD_M + m] = fb[idx];
    }

    // mag = (x+1)^2 staged transposed: magS[h][f]  (LDG coalesced over h; STS stride 130 -> 2-way)
    const float* xp = x + (size_t)fbase * FFT;
    for (int idx = tid; idx < F_TILE * HALF; idx += THREADS) {
        int f = idx / HALF;
        int h = idx - f * HALF;
        float v = __ldg(xp + (size_t)f * FFT + h) + 1.0f;
        magS[h * MPAD_F + f] = v * v;
    }
    __syncthreads();

    const int warp = tid >> 5;
    const int lane = tid & 31;
    const int m0 = warp * 8;   // 8 warps x 8 mels
    const int fl = lane * 4;   // each lane: 4 adjacent local frames

    ull acc[4][4];             // [frame][mel-pair]
    #pragma unroll
    for (int i = 0; i < 4; ++i)
        #pragma unroll
        for (int j = 0; j < 4; ++j) acc[i][j] = 0ull;

    const float* mgp = magS + fl;
    const float* fbp = fbT + m0;

    #pragma unroll 2
    for (int h = 0; h < KPAD; ++h) {
        const float* mrow = mgp + h * MPAD_F;
        float2 ma = *reinterpret_cast<const float2*>(mrow);      // frames fl, fl+1
        float2 mb = *reinterpret_cast<const float2*>(mrow + 2);  // frames fl+2, fl+3
        ull p[4];
        asm("mov.b64 %0, {%1, %1};" : "=l"(p[0]) : "f"(ma.x));
        asm("mov.b64 %0, {%1, %1};" : "=l"(p[1]) : "f"(ma.y));
        asm("mov.b64 %0, {%1, %1};" : "=l"(p[2]) : "f"(mb.x));
        asm("mov.b64 %0, {%1, %1};" : "=l"(p[3]) : "f"(mb.y));

        const float* frow = fbp + h * MPAD_M;                    // warp-broadcast
        ull q[4];
        q[0] = *reinterpret_cast<const ull*>(frow);
        q[1] = *reinterpret_cast<const ull*>(frow + 2);
        q[2] = *reinterpret_cast<const ull*>(frow + 4);
        q[3] = *reinterpret_cast<const ull*>(frow + 6);

        #pragma unroll
        for (int i = 0; i < 4; ++i)
            #pragma unroll
            for (int j = 0; j < 4; ++j)
                FMA2(acc[i][j], p[i], q[j]);                     // 16 independent FMA2
    }

    // epilogue: floor(log2(m)) == IEEE exponent (exact for positive normals)
    #pragma unroll
    for (int i = 0; i < 4; ++i) {
        float r[8];
        #pragma unroll
        for (int j = 0; j < 4; ++j) {
            float lo, hi;
            asm("mov.b64 {%0, %1}, %2;" : "=f"(lo), "=f"(hi) : "l"(acc[i][j]));
            r[2*j]   = lo;
            r[2*j+1] = hi;
        }
        #pragma unroll
        for (int k = 0; k < 8; ++k)
            r[k] = (float)(((__float_as_int(r[k]) >> 23) & 255) - 127);

        size_t g = (size_t)(fbase + fl + i) * NMELS + m0;        // 16B aligned (m0 % 8 == 0)
        float4* o = reinterpret_cast<float4*>(out + g);
        o[0] = make_float4(r[0], r[1], r[2], r[3]);
        o[1] = make_float4(r[4], r[5], r[6], r[7]);
    }
}

extern "C" void kernel_launch(void* const* d_in, const int* in_sizes, int n_in,
                              void* d_out, int out_size)
{
    const float* x  = (const float*)d_in[0];   // (256,256,512,1) fp32
    const float* fb = (const float*)d_in[1];   // (64,257) fp32
    float* out = (float*)d_out;                // (256,256,64,1) fp32

    const int smem = (KPAD * MPAD_M + KPAD * MPAD_F) * (int)sizeof(float);  // 202,272 B
    cudaFuncSetAttribute(lmfe_kernel, cudaFuncAttributeMaxDynamicSharedMemorySize, smem);

    const int nframes = in_sizes[0] / FFT;     // 65536
    const int grid    = nframes / F_TILE;      // 512
    lmfe_kernel<<<grid, THREADS, smem>>>(x, fb, out);
}